// round 1
// baseline (speedup 1.0000x reference)
#include <cuda_runtime.h>
#include <cstddef>

// ForwardSim: B=32768 rows, T=50 steps, MLP 73->128->128->1 with per-row scalar
// carry (ego_v, ego_x, act). Rows are independent across the whole rollout, so
// each CTA owns a 64-row tile persistently: W2 cached in smem once, the
// time-invariant proj_belief@W1[:64]+b1 precomputed once into registers, and
// only 15 floats/row/step streamed from HBM.

namespace {
constexpr int kB = 32768;
constexpr int kT = 50;
constexpr int kH = 128;
constexpr int kM = 64;        // batch rows per CTA
constexpr int kThreads = 256; // 16x16 thread grid, 4x8 per-thread tile
constexpr int kPitch = 132;   // smem pitch (floats) for 128-wide tiles

// shared memory layout (in floats)
constexpr int OFF_W2  = 0;                   // 128 x 132  (phase1: proj tile, pitch 65)
constexpr int OFF_H1  = OFF_W2 + 128 * kPitch; // 64 x 132 (phase1: W1proj, pitch 132)
constexpr int OFF_W1E = OFF_H1 + kM * kPitch;  // 9 x 128
constexpr int OFF_ENV = OFF_W1E + 9 * kH;      // 64 x 12
constexpr int OFF_ACT = OFF_ENV + kM * 12;     // 64
constexpr int OFF_SC  = OFF_ACT + kM;          // 16 (mean[6] @0, inv_std[6] @8)
constexpr int SMEM_FLOATS = OFF_SC + 16;
} // namespace

__global__ void __launch_bounds__(kThreads, 2)
fsim_kernel(const float* __restrict__ proj, const float* __restrict__ idm,
            const float* __restrict__ merg, const float* __restrict__ W1,
            const float* __restrict__ b1,   const float* __restrict__ W2,
            const float* __restrict__ b2,   const float* __restrict__ W3,
            const float* __restrict__ b3,   const float* __restrict__ smean,
            const float* __restrict__ svar, float* __restrict__ out)
{
    extern __shared__ float smem[];
    float* W2s  = smem + OFF_W2;
    float* h1s  = smem + OFF_H1;
    float* W1e  = smem + OFF_W1E;
    float* envs = smem + OFF_ENV;
    float* acts = smem + OFF_ACT;
    float* scal = smem + OFF_SC;

    const int tid = threadIdx.x;
    const int tx  = tid & 15;       // 16 column groups
    const int ty  = tid >> 4;       // 16 row groups
    const int c0  = tx * 8;         // 8 output columns per thread
    const int r0  = ty * 4;         // 4 rows per thread
    const int rowBase = blockIdx.x * kM;

    // ================= phase 1: projAcc = proj_belief @ W1[:64] + b1 ========
    // W1proj rows 0..63 into h1s buffer (pitch 132); proj tile into W2s buffer
    // (pitch 65). Both overwritten afterwards.
    for (int i = tid; i < 64 * kH; i += kThreads)
        h1s[(i >> 7) * kPitch + (i & 127)] = W1[i];
    for (int i = tid; i < kM * 64; i += kThreads) {
        int m = i >> 6, k = i & 63;
        W2s[m * 65 + k] = proj[(size_t)(rowBase + m) * 64 + k];
    }
    __syncthreads();

    float projAcc[4][8];
    #pragma unroll
    for (int c = 0; c < 8; c++) {
        float bv = __ldg(&b1[c0 + c]);
        #pragma unroll
        for (int r = 0; r < 4; r++) projAcc[r][c] = bv;
    }
    #pragma unroll 2
    for (int k = 0; k < 64; k++) {
        float pv[4];
        #pragma unroll
        for (int r = 0; r < 4; r++) pv[r] = W2s[(r0 + r) * 65 + k];
        float4 w0 = *(const float4*)&h1s[k * kPitch + c0];
        float4 w1 = *(const float4*)&h1s[k * kPitch + c0 + 4];
        float wv[8] = {w0.x, w0.y, w0.z, w0.w, w1.x, w1.y, w1.z, w1.w};
        #pragma unroll
        for (int r = 0; r < 4; r++)
            #pragma unroll
            for (int c = 0; c < 8; c++)
                projAcc[r][c] = fmaf(pv[r], wv[c], projAcc[r][c]);
    }
    __syncthreads();

    // ================= load persistent weights ==============================
    for (int i = tid; i < kH * kH; i += kThreads)
        W2s[(i >> 7) * kPitch + (i & 127)] = W2[i];
    for (int i = tid; i < 9 * kH; i += kThreads)
        W1e[i] = W1[64 * kH + i];                 // W1 rows 64..72 (env+mc)
    if (tid < 6) {
        scal[tid]     = smean[tid];
        scal[8 + tid] = rsqrtf(svar[tid]);
    }
    float b2r[8], w3r[8];
    #pragma unroll
    for (int c = 0; c < 8; c++) {
        b2r[c] = __ldg(&b2[c0 + c]);
        w3r[c] = __ldg(&W3[c0 + c]);
    }
    const float b3v = __ldg(&b3[0]);

    float ego_v = 0.f, ego_x = 0.f;   // live only in threads tid < 64
    __syncthreads();

    // ================= timestep loop ========================================
    for (int t = 0; t < kT; t++) {
        // ---- per-row carry update + env features (one thread per row) ----
        if (tid < kM) {
            const int row = rowBase + tid;
            const float* sp = idm + (size_t)row * (kT * 12) + t * 12;
            float4 a0 = *(const float4*)sp;         // s0 s1 s2 s3
            float4 a1 = *(const float4*)(sp + 4);   // s4 s5 s6 s7
            float s11 = sp[11];
            if (t == 0) {
                ego_v = a0.x;
                ego_x = a0.w;
            } else {
                float a = acts[tid];
                ego_v = fmaf(a, 0.1f, ego_v);
                ego_x = ego_x + ego_v * 0.1f + a * 0.005f;
            }
            float ev[6];
            ev[0] = ego_v;                                       // ego_v
            ev[1] = a0.y;                                        // f_veh_v
            ev[2] = ego_v - a0.y;                                // ef_dv
            ev[3] = a1.x - ego_x;                                // ef_delta_x
            ev[4] = (ego_v - a0.z) * s11;                        // em_dv
            ev[5] = (a1.y - ego_x) * s11 + (1.0f - s11) * 100.0f; // em_delta_x
            #pragma unroll
            for (int k = 0; k < 6; k++)
                envs[tid * 12 + k] = (ev[k] - scal[k]) * scal[8 + k];
            const float* mp = merg + (size_t)row * (kT * 3) + t * 3;
            envs[tid * 12 + 6] = mp[0];
            envs[tid * 12 + 7] = mp[1];
            envs[tid * 12 + 8] = mp[2];
        }
        __syncthreads();

        // ---- h1 = relu(projAcc + [env,mc] @ W1[64:73]) -> smem ----
        {
            float hv[4][8];
            #pragma unroll
            for (int r = 0; r < 4; r++)
                #pragma unroll
                for (int c = 0; c < 8; c++) hv[r][c] = projAcc[r][c];
            #pragma unroll
            for (int k = 0; k < 9; k++) {
                float evv[4];
                #pragma unroll
                for (int r = 0; r < 4; r++) evv[r] = envs[(r0 + r) * 12 + k];
                float4 w0 = *(const float4*)&W1e[k * kH + c0];
                float4 w1 = *(const float4*)&W1e[k * kH + c0 + 4];
                float wv[8] = {w0.x, w0.y, w0.z, w0.w, w1.x, w1.y, w1.z, w1.w};
                #pragma unroll
                for (int r = 0; r < 4; r++)
                    #pragma unroll
                    for (int c = 0; c < 8; c++)
                        hv[r][c] = fmaf(evv[r], wv[c], hv[r][c]);
            }
            #pragma unroll
            for (int r = 0; r < 4; r++) {
                float4 o0, o1;
                o0.x = fmaxf(hv[r][0], 0.f); o0.y = fmaxf(hv[r][1], 0.f);
                o0.z = fmaxf(hv[r][2], 0.f); o0.w = fmaxf(hv[r][3], 0.f);
                o1.x = fmaxf(hv[r][4], 0.f); o1.y = fmaxf(hv[r][5], 0.f);
                o1.z = fmaxf(hv[r][6], 0.f); o1.w = fmaxf(hv[r][7], 0.f);
                *(float4*)&h1s[(r0 + r) * kPitch + c0]     = o0;
                *(float4*)&h1s[(r0 + r) * kPitch + c0 + 4] = o1;
            }
        }
        __syncthreads();

        // ---- h2 = relu(h1 @ W2 + b2) : 128x128 GEMM, the hot loop ----
        float acc[4][8];
        #pragma unroll
        for (int r = 0; r < 4; r++)
            #pragma unroll
            for (int c = 0; c < 8; c++) acc[r][c] = b2r[c];
        #pragma unroll 2
        for (int k = 0; k < kH; k++) {
            float av[4];
            #pragma unroll
            for (int r = 0; r < 4; r++) av[r] = h1s[(r0 + r) * kPitch + k];
            float4 w0 = *(const float4*)&W2s[k * kPitch + c0];
            float4 w1 = *(const float4*)&W2s[k * kPitch + c0 + 4];
            float wv[8] = {w0.x, w0.y, w0.z, w0.w, w1.x, w1.y, w1.z, w1.w};
            #pragma unroll
            for (int r = 0; r < 4; r++)
                #pragma unroll
                for (int c = 0; c < 8; c++)
                    acc[r][c] = fmaf(av[r], wv[c], acc[r][c]);
        }

        // ---- act = relu(h2) @ W3 + b3 ; reduce across the 16 column threads
        float pact[4];
        #pragma unroll
        for (int r = 0; r < 4; r++) {
            float s = 0.f;
            #pragma unroll
            for (int c = 0; c < 8; c++)
                s = fmaf(fmaxf(acc[r][c], 0.f), w3r[c], s);
            pact[r] = s;
        }
        #pragma unroll
        for (int off = 8; off >= 1; off >>= 1)
            #pragma unroll
            for (int r = 0; r < 4; r++)
                pact[r] += __shfl_xor_sync(0xFFFFFFFFu, pact[r], off, 16);
        if (tx == 0) {
            #pragma unroll
            for (int r = 0; r < 4; r++) {
                float a = pact[r] + b3v;
                acts[r0 + r] = a;
                out[(size_t)(rowBase + r0 + r) * kT + t] = a;
            }
        }
        __syncthreads();
    }
}

extern "C" void kernel_launch(void* const* d_in, const int* in_sizes, int n_in,
                              void* d_out, int out_size)
{
    (void)in_sizes; (void)n_in; (void)out_size;
    const float* proj  = (const float*)d_in[0];   // (B, 64)
    const float* idm   = (const float*)d_in[1];   // (B, T, 12)
    const float* merg  = (const float*)d_in[2];   // (B, T, 3)
    const float* W1    = (const float*)d_in[3];   // (73, 128)
    const float* b1    = (const float*)d_in[4];   // (128,)
    const float* W2    = (const float*)d_in[5];   // (128, 128)
    const float* b2    = (const float*)d_in[6];   // (128,)
    const float* W3    = (const float*)d_in[7];   // (128, 1)
    const float* b3    = (const float*)d_in[8];   // (1,)
    const float* smean = (const float*)d_in[9];   // (6,)
    const float* svar  = (const float*)d_in[10];  // (6,)
    float* out = (float*)d_out;                   // (B, T, 1) fp32

    const size_t smemBytes = (size_t)SMEM_FLOATS * sizeof(float); // ~107 KB
    cudaFuncSetAttribute(fsim_kernel,
                         cudaFuncAttributeMaxDynamicSharedMemorySize,
                         (int)smemBytes);
    fsim_kernel<<<kB / kM, kThreads, smemBytes>>>(
        proj, idm, merg, W1, b1, W2, b2, W3, b3, smean, svar, out);
}